// round 6
// baseline (speedup 1.0000x reference)
#include <cuda_runtime.h>

#define NN 100000
#define NE 1600000

// ---------------- scratch (device globals; no allocation allowed) ----------
__device__ float g_hn[NN * 64];   // h @ W_neigh (transformed features to gather)
__device__ int   g_deg [NN];
__device__ int   g_off [NN];
__device__ int   g_cur [NN];
__device__ int   g_srcs[NE];      // CSR-by-dst src list
__device__ int   g_is64;          // 1 if edge_index is int64, 0 if int32

// ---------------- dtype sniffer -------------------------------------------
// int64 node ids < 2^31  => every odd 32-bit word (high half) is 0.
// int32 ids: odd words are random node ids; all-zero prob ~ 1e-160.
__global__ void sniff_k(const int* __restrict__ ei32) {
    int v = ei32[2 * threadIdx.x + 1];
    unsigned m = __ballot_sync(0xffffffffu, v != 0);
    if (threadIdx.x == 0) g_is64 = (m == 0) ? 1 : 0;
}

// ---------------- graph preprocessing (once per launch) --------------------
__global__ void zero_deg_k() {
    int i = blockIdx.x * blockDim.x + threadIdx.x;
    if (i < NN) g_deg[i] = 0;
}

__global__ void hist_k(const int* __restrict__ ei32) {
    int e = blockIdx.x * blockDim.x + threadIdx.x;
    if (e < NE) {
        int dst = g_is64 ? ei32[2 * (NE + e)] : ei32[NE + e];
        atomicAdd(&g_deg[dst], 1);
    }
}

// single-block (256 threads) exclusive scan over g_deg -> g_off, g_cur
__global__ void scan_k() {
    __shared__ int sums[256];
    const int tid = threadIdx.x;
    const int CHUNK = (NN + 255) / 256;   // 391
    int start = tid * CHUNK;
    int end = start + CHUNK;
    if (end > NN) end = NN;
    if (start > NN) start = NN;
    int s = 0;
    for (int i = start; i < end; i++) s += g_deg[i];
    sums[tid] = s;
    __syncthreads();
    for (int d = 1; d < 256; d <<= 1) {
        int t = (tid >= d) ? sums[tid - d] : 0;
        __syncthreads();
        sums[tid] += t;
        __syncthreads();
    }
    int pre = sums[tid] - s;   // exclusive prefix of this chunk
    for (int i = start; i < end; i++) {
        g_off[i] = pre;
        g_cur[i] = pre;
        pre += g_deg[i];
    }
}

__global__ void scatter_k(const int* __restrict__ ei32) {
    int e = blockIdx.x * blockDim.x + threadIdx.x;
    if (e < NE) {
        int src, dst;
        if (g_is64) {
            src = ei32[2 * e];
            dst = ei32[2 * (NE + e)];
        } else {
            src = ei32[e];
            dst = ei32[NE + e];
        }
        int pos = atomicAdd(&g_cur[dst], 1);
        g_srcs[pos] = src;
    }
}

// ---------------- dual GEMM (DOUT=64): hs -> out region, hn -> g_hn --------
// 128 threads / block, 32 rows / block. DIN = 64. Optional relu on input.
__global__ void gemm64_k(const float* __restrict__ hin,
                         const float* __restrict__ Ws,
                         const float* __restrict__ Wn,
                         float* __restrict__ hs_out,
                         int relu_in) {
    __shared__ float sh_h[32][65];
    __shared__ float sh_ws[64 * 64];
    __shared__ float sh_wn[64 * 64];

    const int tid  = threadIdx.x;
    const int row0 = blockIdx.x * 32;

    for (int i = tid; i < 64 * 64; i += 128) {
        sh_ws[i] = Ws[i];
        sh_wn[i] = Wn[i];
    }
    for (int i = tid; i < 32 * 64; i += 128) {
        int r = i >> 6, c = i & 63;
        int gr = row0 + r;
        float v = (gr < NN) ? hin[gr * 64 + c] : 0.f;
        if (relu_in) v = fmaxf(v, 0.f);
        sh_h[r][c] = v;
    }
    __syncthreads();

    const int tx = tid & 7;      // 8 column groups x 8 cols
    const int ty = tid >> 3;     // 16 row groups x 2 rows
    const int r0 = ty * 2;

    float accs[2][8], accn[2][8];
#pragma unroll
    for (int r = 0; r < 2; r++)
#pragma unroll
        for (int j = 0; j < 8; j++) { accs[r][j] = 0.f; accn[r][j] = 0.f; }

#pragma unroll 8
    for (int k = 0; k < 64; k++) {
        float h0 = sh_h[r0][k];
        float h1 = sh_h[r0 + 1][k];
#pragma unroll
        for (int j = 0; j < 8; j++) {
            float ws = sh_ws[k * 64 + tx * 8 + j];
            float wn = sh_wn[k * 64 + tx * 8 + j];
            accs[0][j] = fmaf(h0, ws, accs[0][j]);
            accs[1][j] = fmaf(h1, ws, accs[1][j]);
            accn[0][j] = fmaf(h0, wn, accn[0][j]);
            accn[1][j] = fmaf(h1, wn, accn[1][j]);
        }
    }

#pragma unroll
    for (int r = 0; r < 2; r++) {
        int gr = row0 + r0 + r;
        if (gr < NN) {
#pragma unroll
            for (int j = 0; j < 8; j++) {
                hs_out[gr * 64 + tx * 8 + j] = accs[r][j];
                g_hn [gr * 64 + tx * 8 + j] = accn[r][j];
            }
        }
    }
}

// ---------------- dual GEMM (DOUT=16) --------------------------------------
__global__ void gemm16_k(const float* __restrict__ hin,
                         const float* __restrict__ Ws,
                         const float* __restrict__ Wn,
                         float* __restrict__ hs_out,
                         int relu_in) {
    __shared__ float sh_h[32][65];
    __shared__ float sh_ws[64 * 16];
    __shared__ float sh_wn[64 * 16];

    const int tid  = threadIdx.x;
    const int row0 = blockIdx.x * 32;

    for (int i = tid; i < 64 * 16; i += 128) {
        sh_ws[i] = Ws[i];
        sh_wn[i] = Wn[i];
    }
    for (int i = tid; i < 32 * 64; i += 128) {
        int r = i >> 6, c = i & 63;
        int gr = row0 + r;
        float v = (gr < NN) ? hin[gr * 64 + c] : 0.f;
        if (relu_in) v = fmaxf(v, 0.f);
        sh_h[r][c] = v;
    }
    __syncthreads();

    const int tx = tid & 7;      // 8 column groups x 2 cols
    const int ty = tid >> 3;     // 16 row groups x 2 rows
    const int r0 = ty * 2;

    float accs[2][2], accn[2][2];
#pragma unroll
    for (int r = 0; r < 2; r++)
#pragma unroll
        for (int j = 0; j < 2; j++) { accs[r][j] = 0.f; accn[r][j] = 0.f; }

#pragma unroll 8
    for (int k = 0; k < 64; k++) {
        float h0 = sh_h[r0][k];
        float h1 = sh_h[r0 + 1][k];
#pragma unroll
        for (int j = 0; j < 2; j++) {
            float ws = sh_ws[k * 16 + tx * 2 + j];
            float wn = sh_wn[k * 16 + tx * 2 + j];
            accs[0][j] = fmaf(h0, ws, accs[0][j]);
            accs[1][j] = fmaf(h1, ws, accs[1][j]);
            accn[0][j] = fmaf(h0, wn, accn[0][j]);
            accn[1][j] = fmaf(h1, wn, accn[1][j]);
        }
    }

#pragma unroll
    for (int r = 0; r < 2; r++) {
        int gr = row0 + r0 + r;
        if (gr < NN) {
#pragma unroll
            for (int j = 0; j < 2; j++) {
                hs_out[gr * 16 + tx * 2 + j] = accs[r][j];
                g_hn [gr * 16 + tx * 2 + j] = accn[r][j];
            }
        }
    }
}

// ---------------- fused aggregation + epilogue (RMW into out) --------------
// One warp per dst node; outp already holds h@W_self for that node.
__global__ void agg64_k(const float* __restrict__ b,
                        float* __restrict__ outp) {
    const int gw   = (blockIdx.x * blockDim.x + threadIdx.x) >> 5;
    const int lane = threadIdx.x & 31;
    if (gw >= NN) return;
    const int beg = g_off[gw];
    const int deg = g_deg[gw];
    const float inv = (deg > 0) ? (1.f / (float)deg) : 1.f;

    float a0 = 0.f, a1 = 0.f;
    for (int i = 0; i < deg; i++) {
        int src = g_srcs[beg + i];            // broadcast across warp
        a0 += g_hn[src * 64 + lane];          // coalesced 128B
        a1 += g_hn[src * 64 + 32 + lane];     // coalesced 128B
    }
    const int o = gw * 64;
    outp[o + lane]      += a0 * inv + b[lane];
    outp[o + 32 + lane] += a1 * inv + b[32 + lane];
}

// 16 threads per dst (2 dsts per warp)
__global__ void agg16_k(const float* __restrict__ b,
                        float* __restrict__ outp) {
    const int t = blockIdx.x * blockDim.x + threadIdx.x;
    const int dst = t >> 4;
    const int l   = t & 15;
    if (dst >= NN) return;
    const int beg = g_off[dst];
    const int deg = g_deg[dst];
    const float inv = (deg > 0) ? (1.f / (float)deg) : 1.f;

    float a = 0.f;
    for (int i = 0; i < deg; i++) {
        int src = g_srcs[beg + i];
        a += g_hn[src * 16 + l];
    }
    outp[dst * 16 + l] += a * inv + b[l];
}

// ---------------- launch ---------------------------------------------------
extern "C" void kernel_launch(void* const* d_in, const int* in_sizes, int n_in,
                              void* d_out, int out_size) {
    const float* feat = (const float*)d_in[0];
    const int*   ei32 = (const int*)d_in[1];     // int32 OR int64 (sniffed)
    const float* Ws0 = (const float*)d_in[2];
    const float* Wn0 = (const float*)d_in[3];
    const float* b0  = (const float*)d_in[4];
    const float* Ws1 = (const float*)d_in[5];
    const float* Wn1 = (const float*)d_in[6];
    const float* b1  = (const float*)d_in[7];
    const float* Ws2 = (const float*)d_in[8];
    const float* Wn2 = (const float*)d_in[9];
    const float* b2  = (const float*)d_in[10];

    float* out    = (float*)d_out;
    float* out_h  = out;                          // [NN,16] final logits
    float* out_e0 = out + NN * 16;                // [NN,64] embed0 (pre-relu L0)
    float* out_e1 = out + NN * 16 + NN * 64;      // [NN,64] embed1 (pre-relu L1)

    const int TB = 256;
    // --- detect edge_index dtype, then build CSR-by-dst once ---
    sniff_k<<<1, 32>>>(ei32);
    zero_deg_k<<<(NN + TB - 1) / TB, TB>>>();
    hist_k<<<(NE + TB - 1) / TB, TB>>>(ei32);
    scan_k<<<1, 256>>>();
    scatter_k<<<(NE + TB - 1) / TB, TB>>>(ei32);

    const int GEMM_BLOCKS  = (NN + 31) / 32;              // 3125
    const int AGG64_BLOCKS = (NN * 32 + TB - 1) / TB;     // 1 warp / dst
    const int AGG16_BLOCKS = (NN * 16 + TB - 1) / TB;     // 16 thr / dst

    // --- layer 0: feat -> embed0 (pre-relu) ---
    gemm64_k<<<GEMM_BLOCKS, 128>>>(feat, Ws0, Wn0, out_e0, 0);
    agg64_k<<<AGG64_BLOCKS, TB>>>(b0, out_e0);

    // --- layer 1: relu(embed0) -> embed1 (pre-relu) ---
    gemm64_k<<<GEMM_BLOCKS, 128>>>(out_e0, Ws1, Wn1, out_e1, 1);
    agg64_k<<<AGG64_BLOCKS, TB>>>(b1, out_e1);

    // --- layer 2: relu(embed1) -> logits (16 classes, no relu) ---
    gemm16_k<<<GEMM_BLOCKS, 128>>>(out_e1, Ws2, Wn2, out_h, 1);
    agg16_k<<<AGG16_BLOCKS, TB>>>(b2, out_h);
}

// round 9
// speedup vs baseline: 1.8520x; 1.8520x over previous
#include <cuda_runtime.h>

#define NN 100000
#define NE 1600000
#define NB_SCAN ((NN + 255) / 256)   // 391 scan blocks

// ---------------- scratch (device globals; no allocation allowed) ----------
__device__ float g_hn[NN * 64];   // h @ W_neigh (transformed features to gather)
__device__ int   g_deg [NN];
__device__ int   g_off [NN];
__device__ int   g_cur [NN];
__device__ int   g_srcs[NE];      // CSR-by-dst src list
__device__ int   g_is64;          // 1 if edge_index is int64, 0 if int32
__device__ int   g_bsum[512];     // per-block sums for hierarchical scan
__device__ int   g_bpre[512];     // exclusive prefix of block sums

// ---------------- dtype sniffer -------------------------------------------
// int64 node ids < 2^31 => every odd 32-bit word (high half) is 0.
__global__ void sniff_k(const int* __restrict__ ei32) {
    int v = ei32[2 * threadIdx.x + 1];
    unsigned m = __ballot_sync(0xffffffffu, v != 0);
    if (threadIdx.x == 0) g_is64 = (m == 0) ? 1 : 0;
}

// ---------------- graph preprocessing (once per launch) --------------------
__global__ void zero_deg_k() {
    int i = blockIdx.x * blockDim.x + threadIdx.x;
    if (i < NN) g_deg[i] = 0;
}

__global__ void hist_k(const int* __restrict__ ei32) {
    int e = blockIdx.x * blockDim.x + threadIdx.x;
    if (e < NE) {
        int dst = g_is64 ? ei32[2 * (NE + e)] : ei32[NE + e];
        atomicAdd(&g_deg[dst], 1);
    }
}

// ---- hierarchical scan: local scan + block sums ----------------------------
__global__ void scan1_k() {
    __shared__ int s[256];
    const int tid = threadIdx.x;
    const int i = blockIdx.x * 256 + tid;
    int v = (i < NN) ? g_deg[i] : 0;
    s[tid] = v;
    __syncthreads();
    for (int d = 1; d < 256; d <<= 1) {
        int t = (tid >= d) ? s[tid - d] : 0;
        __syncthreads();
        s[tid] += t;
        __syncthreads();
    }
    if (i < NN) g_off[i] = s[tid] - v;           // local exclusive prefix
    if (tid == 255) g_bsum[blockIdx.x] = s[255]; // block total
}

// ---- scan the 391 block sums in one block ----------------------------------
__global__ void scan2_k() {
    __shared__ int s[512];
    const int tid = threadIdx.x;
    int v = (tid < NB_SCAN) ? g_bsum[tid] : 0;
    s[tid] = v;
    __syncthreads();
    for (int d = 1; d < 512; d <<= 1) {
        int t = (tid >= d) ? s[tid - d] : 0;
        __syncthreads();
        s[tid] += t;
        __syncthreads();
    }
    if (tid < NB_SCAN) g_bpre[tid] = s[tid] - v; // exclusive block prefix
}

// ---- add block prefixes, produce g_off / g_cur -----------------------------
__global__ void scan3_k() {
    const int i = blockIdx.x * 256 + threadIdx.x;
    if (i < NN) {
        int o = g_off[i] + g_bpre[blockIdx.x];
        g_off[i] = o;
        g_cur[i] = o;
    }
}

__global__ void scatter_k(const int* __restrict__ ei32) {
    int e = blockIdx.x * blockDim.x + threadIdx.x;
    if (e < NE) {
        int src, dst;
        if (g_is64) {
            src = ei32[2 * e];
            dst = ei32[2 * (NE + e)];
        } else {
            src = ei32[e];
            dst = ei32[NE + e];
        }
        int pos = atomicAdd(&g_cur[dst], 1);
        g_srcs[pos] = src;
    }
}

// ---------------- dual GEMM (DOUT=64): hs -> out region, hn -> g_hn --------
// 128 threads / block, 64 rows / block, 4 rows x 8 cols per thread.
// sh_h is XOR-swizzled (r*64 + (c^r)) for conflict-free column reads, no pad.
__global__ void gemm64_k(const float* __restrict__ hin,
                         const float* __restrict__ Ws,
                         const float* __restrict__ Wn,
                         float* __restrict__ hs_out,
                         int relu_in) {
    __shared__ float sh_h [64 * 64];
    __shared__ float sh_ws[64 * 64];
    __shared__ float sh_wn[64 * 64];

    const int tid  = threadIdx.x;
    const int row0 = blockIdx.x * 64;

    {   // weights: 16KB each, float4 loads
        const float4* Ws4 = (const float4*)Ws;
        const float4* Wn4 = (const float4*)Wn;
        float4* sws4 = (float4*)sh_ws;
        float4* swn4 = (float4*)sh_wn;
        for (int i = tid; i < 1024; i += 128) {
            sws4[i] = Ws4[i];
            swn4[i] = Wn4[i];
        }
    }
    for (int i = tid; i < 64 * 64; i += 128) {
        int r = i >> 6, c = i & 63;
        int gr = row0 + r;
        float v = (gr < NN) ? hin[gr * 64 + c] : 0.f;
        if (relu_in) v = fmaxf(v, 0.f);
        sh_h[r * 64 + (c ^ r)] = v;
    }
    __syncthreads();

    const int tx = tid & 7;      // 8 column groups x 8 cols
    const int ty = tid >> 3;     // 16 row groups x 4 rows
    const int r0 = ty * 4;

    float accs[4][8], accn[4][8];
#pragma unroll
    for (int r = 0; r < 4; r++)
#pragma unroll
        for (int j = 0; j < 8; j++) { accs[r][j] = 0.f; accn[r][j] = 0.f; }

    for (int k = 0; k < 64; k++) {
        float4 ws0 = *(const float4*)&sh_ws[k * 64 + tx * 8];
        float4 ws1 = *(const float4*)&sh_ws[k * 64 + tx * 8 + 4];
        float4 wn0 = *(const float4*)&sh_wn[k * 64 + tx * 8];
        float4 wn1 = *(const float4*)&sh_wn[k * 64 + tx * 8 + 4];
        float hv[4];
#pragma unroll
        for (int r = 0; r < 4; r++)
            hv[r] = sh_h[(r0 + r) * 64 + (k ^ (r0 + r))];
#pragma unroll
        for (int r = 0; r < 4; r++) {
            accs[r][0] = fmaf(hv[r], ws0.x, accs[r][0]);
            accs[r][1] = fmaf(hv[r], ws0.y, accs[r][1]);
            accs[r][2] = fmaf(hv[r], ws0.z, accs[r][2]);
            accs[r][3] = fmaf(hv[r], ws0.w, accs[r][3]);
            accs[r][4] = fmaf(hv[r], ws1.x, accs[r][4]);
            accs[r][5] = fmaf(hv[r], ws1.y, accs[r][5]);
            accs[r][6] = fmaf(hv[r], ws1.z, accs[r][6]);
            accs[r][7] = fmaf(hv[r], ws1.w, accs[r][7]);
            accn[r][0] = fmaf(hv[r], wn0.x, accn[r][0]);
            accn[r][1] = fmaf(hv[r], wn0.y, accn[r][1]);
            accn[r][2] = fmaf(hv[r], wn0.z, accn[r][2]);
            accn[r][3] = fmaf(hv[r], wn0.w, accn[r][3]);
            accn[r][4] = fmaf(hv[r], wn1.x, accn[r][4]);
            accn[r][5] = fmaf(hv[r], wn1.y, accn[r][5]);
            accn[r][6] = fmaf(hv[r], wn1.z, accn[r][6]);
            accn[r][7] = fmaf(hv[r], wn1.w, accn[r][7]);
        }
    }

#pragma unroll
    for (int r = 0; r < 4; r++) {
        int gr = row0 + r0 + r;
        if (gr < NN) {
            float4* o0 = (float4*)&hs_out[gr * 64 + tx * 8];
            float4* n0 = (float4*)&g_hn [gr * 64 + tx * 8];
            o0[0] = make_float4(accs[r][0], accs[r][1], accs[r][2], accs[r][3]);
            o0[1] = make_float4(accs[r][4], accs[r][5], accs[r][6], accs[r][7]);
            n0[0] = make_float4(accn[r][0], accn[r][1], accn[r][2], accn[r][3]);
            n0[1] = make_float4(accn[r][4], accn[r][5], accn[r][6], accn[r][7]);
        }
    }
}

// ---------------- dual GEMM (DOUT=16) --------------------------------------
__global__ void gemm16_k(const float* __restrict__ hin,
                         const float* __restrict__ Ws,
                         const float* __restrict__ Wn,
                         float* __restrict__ hs_out,
                         int relu_in) {
    __shared__ float sh_h[32][65];
    __shared__ float sh_ws[64 * 16];
    __shared__ float sh_wn[64 * 16];

    const int tid  = threadIdx.x;
    const int row0 = blockIdx.x * 32;

    for (int i = tid; i < 64 * 16; i += 128) {
        sh_ws[i] = Ws[i];
        sh_wn[i] = Wn[i];
    }
    for (int i = tid; i < 32 * 64; i += 128) {
        int r = i >> 6, c = i & 63;
        int gr = row0 + r;
        float v = (gr < NN) ? hin[gr * 64 + c] : 0.f;
        if (relu_in) v = fmaxf(v, 0.f);
        sh_h[r][c] = v;
    }
    __syncthreads();

    const int tx = tid & 7;      // 8 column groups x 2 cols
    const int ty = tid >> 3;     // 16 row groups x 2 rows
    const int r0 = ty * 2;

    float accs[2][2], accn[2][2];
#pragma unroll
    for (int r = 0; r < 2; r++)
#pragma unroll
        for (int j = 0; j < 2; j++) { accs[r][j] = 0.f; accn[r][j] = 0.f; }

#pragma unroll 8
    for (int k = 0; k < 64; k++) {
        float h0 = sh_h[r0][k];
        float h1 = sh_h[r0 + 1][k];
#pragma unroll
        for (int j = 0; j < 2; j++) {
            float ws = sh_ws[k * 16 + tx * 2 + j];
            float wn = sh_wn[k * 16 + tx * 2 + j];
            accs[0][j] = fmaf(h0, ws, accs[0][j]);
            accs[1][j] = fmaf(h1, ws, accs[1][j]);
            accn[0][j] = fmaf(h0, wn, accn[0][j]);
            accn[1][j] = fmaf(h1, wn, accn[1][j]);
        }
    }

#pragma unroll
    for (int r = 0; r < 2; r++) {
        int gr = row0 + r0 + r;
        if (gr < NN) {
#pragma unroll
            for (int j = 0; j < 2; j++) {
                hs_out[gr * 16 + tx * 2 + j] = accs[r][j];
                g_hn [gr * 16 + tx * 2 + j] = accn[r][j];
            }
        }
    }
}

// ---------------- fused aggregation + epilogue (RMW into out) --------------
// One warp per dst; 2 edges per iteration; each lane reads one float4.
// Lanes 0-15 cover edge i, lanes 16-31 cover edge i+1; halves merged by shfl.
__global__ void agg64_k(const float* __restrict__ b,
                        float* __restrict__ outp) {
    const int gw   = (blockIdx.x * blockDim.x + threadIdx.x) >> 5;
    const int lane = threadIdx.x & 31;
    if (gw >= NN) return;
    const int beg  = g_off[gw];
    const int deg  = g_deg[gw];
    const float inv = (deg > 0) ? (1.f / (float)deg) : 1.f;

    const int half = lane >> 4;     // 0 or 1
    const int l4   = lane & 15;     // float4 slot within the 64-float row
    const float4* __restrict__ hn4 = (const float4*)g_hn;

    float ax = 0.f, ay = 0.f, az = 0.f, aw = 0.f;
    int i = 0;
    for (; i + 2 <= deg; i += 2) {
        int src = g_srcs[beg + i + half];
        float4 v = hn4[src * 16 + l4];
        ax += v.x; ay += v.y; az += v.z; aw += v.w;
    }
    if (i < deg && half == 0) {
        int src = g_srcs[beg + i];
        float4 v = hn4[src * 16 + l4];
        ax += v.x; ay += v.y; az += v.z; aw += v.w;
    }
    // fold upper half into lower half
    ax += __shfl_down_sync(0xffffffffu, ax, 16);
    ay += __shfl_down_sync(0xffffffffu, ay, 16);
    az += __shfl_down_sync(0xffffffffu, az, 16);
    aw += __shfl_down_sync(0xffffffffu, aw, 16);

    if (half == 0) {
        float4* op = (float4*)&outp[gw * 64];
        const float4* b4 = (const float4*)b;
        float4 o  = op[l4];
        float4 bb = b4[l4];
        o.x += ax * inv + bb.x;
        o.y += ay * inv + bb.y;
        o.z += az * inv + bb.z;
        o.w += aw * inv + bb.w;
        op[l4] = o;
    }
}

// 16 threads per dst (2 dsts per warp)
__global__ void agg16_k(const float* __restrict__ b,
                        float* __restrict__ outp) {
    const int t = blockIdx.x * blockDim.x + threadIdx.x;
    const int dst = t >> 4;
    const int l   = t & 15;
    if (dst >= NN) return;
    const int beg = g_off[dst];
    const int deg = g_deg[dst];
    const float inv = (deg > 0) ? (1.f / (float)deg) : 1.f;

    float a = 0.f;
    for (int i = 0; i < deg; i++) {
        int src = g_srcs[beg + i];
        a += g_hn[src * 16 + l];
    }
    outp[dst * 16 + l] += a * inv + b[l];
}

// ---------------- launch ---------------------------------------------------
extern "C" void kernel_launch(void* const* d_in, const int* in_sizes, int n_in,
                              void* d_out, int out_size) {
    const float* feat = (const float*)d_in[0];
    const int*   ei32 = (const int*)d_in[1];     // int32 OR int64 (sniffed)
    const float* Ws0 = (const float*)d_in[2];
    const float* Wn0 = (const float*)d_in[3];
    const float* b0  = (const float*)d_in[4];
    const float* Ws1 = (const float*)d_in[5];
    const float* Wn1 = (const float*)d_in[6];
    const float* b1  = (const float*)d_in[7];
    const float* Ws2 = (const float*)d_in[8];
    const float* Wn2 = (const float*)d_in[9];
    const float* b2  = (const float*)d_in[10];

    float* out    = (float*)d_out;
    float* out_h  = out;                          // [NN,16] final logits
    float* out_e0 = out + NN * 16;                // [NN,64] embed0 (pre-relu L0)
    float* out_e1 = out + NN * 16 + NN * 64;      // [NN,64] embed1 (pre-relu L1)

    const int TB = 256;
    // --- detect edge_index dtype, then build CSR-by-dst once ---
    sniff_k<<<1, 32>>>(ei32);
    zero_deg_k<<<(NN + TB - 1) / TB, TB>>>();
    hist_k<<<(NE + TB - 1) / TB, TB>>>(ei32);
    scan1_k<<<NB_SCAN, 256>>>();
    scan2_k<<<1, 512>>>();
    scan3_k<<<NB_SCAN, 256>>>();
    scatter_k<<<(NE + TB - 1) / TB, TB>>>(ei32);

    const int GEMM64_BLOCKS = (NN + 63) / 64;             // 1563
    const int GEMM16_BLOCKS = (NN + 31) / 32;             // 3125
    const int AGG64_BLOCKS  = (NN * 32 + TB - 1) / TB;    // 1 warp / dst
    const int AGG16_BLOCKS  = (NN * 16 + TB - 1) / TB;    // 16 thr / dst

    // --- layer 0: feat -> embed0 (pre-relu) ---
    gemm64_k<<<GEMM64_BLOCKS, 128>>>(feat, Ws0, Wn0, out_e0, 0);
    agg64_k<<<AGG64_BLOCKS, TB>>>(b0, out_e0);

    // --- layer 1: relu(embed0) -> embed1 (pre-relu) ---
    gemm64_k<<<GEMM64_BLOCKS, 128>>>(out_e0, Ws1, Wn1, out_e1, 1);
    agg64_k<<<AGG64_BLOCKS, TB>>>(b1, out_e1);

    // --- layer 2: relu(embed1) -> logits (16 classes, no relu) ---
    gemm16_k<<<GEMM16_BLOCKS, 128>>>(out_e1, Ws2, Wn2, out_h, 1);
    agg16_k<<<AGG16_BLOCKS, TB>>>(b2, out_h);
}